// round 12
// baseline (speedup 1.0000x reference)
#include <cuda_runtime.h>
#include <math.h>

// Tropical (max-plus) depthwise 5x5 conv, stride 1, pad 2 (-inf), dilation 1.
// x: [8,32,224,224] f32, kernel: [32,1,5,5] f32, out same shape.
// out[b,c,h,w] = max_{i,j} ( x_pad[b,c,h+i,w+j] + kflip[c,i,j] ),
// kflip[c,i,j] = kernel[c,0,4-i,4-j].
//
// R10: CTA-cooperative smem tiling.
//  - CTA = 224 threads = one plane's 224-wide x 32-tall output tile.
//    grid = (7 row-tiles, 256 planes).
//  - Phase 1: stage input rows [tile*32-2 .. tile*32+33] into smem as a
//    36 x 228 array (smem col = global col + 2; cols 0,1,226,227 = -inf,
//    out-of-range rows = -inf). 36 coalesced LDG+STS per thread, high MLP.
//  - Phase 2: streaming 4-wide x 8-tall per-thread tile (56 col-groups x
//    4 row-groups). v[8] = two ALIGNED conflict-free LDS.128 per input row
//    (29-cyc latency vs 234 LDG) -- no predication, no -inf fills.
//    Outputs unshifted -> 8 unpredicated STG.128 per thread.
//  - Weights in registers (CTA single-plane -> warp-uniform broadcast LDG).
//  - Cyclic 5-row accumulator window + balanced max trees (i==0 init fusion).
//  - __launch_bounds__(224,5): 56-reg cap, 32.8KB smem -> 5 CTAs/SM.

#define HW 224
#define SROW 228                 // smem row stride in floats
#define NEG_INF (-INFINITY)

__global__ __launch_bounds__(224, 5) void tropical_conv_kernel(
    const float* __restrict__ x,
    const float* __restrict__ w,
    float* __restrict__ out)
{
    __shared__ float sx[36 * SROW];         // 32832 B

    const int tid   = threadIdx.x;          // 0..223
    const int tile  = blockIdx.x;           // 0..6  (rows tile*32 .. tile*32+31)
    const int plane = blockIdx.y;           // 0..255 (b*32 + c)
    const int c     = plane & 31;

    const float* xp = x + (size_t)plane * (HW * HW);

    // ---- Phase 1: stage input window into smem ----
    const int trow0 = tile * 32 - 2;        // global row of smem row 0
#pragma unroll 4
    for (int rr = 0; rr < 36; rr++) {
        const int gr = trow0 + rr;
        const float val = (gr >= 0 && gr < HW) ? __ldg(&xp[gr * HW + tid]) : NEG_INF;
        sx[rr * SROW + 2 + tid] = val;
    }
    // halo columns: tid 0,1 -> smem cols 0,1 ; tid 2,3 -> smem cols 226,227
    if (tid < 4) {
        const int col = (tid < 2) ? tid : (224 + tid);
#pragma unroll 4
        for (int rr = 0; rr < 36; rr++)
            sx[rr * SROW + col] = NEG_INF;
    }

    // Flipped weights (warp-uniform -> broadcast loads)
    float wf[25];
#pragma unroll
    for (int i = 0; i < 5; i++)
#pragma unroll
        for (int j = 0; j < 5; j++)
            wf[i * 5 + j] = __ldg(&w[c * 25 + (4 - i) * 5 + (4 - j)]);

    __syncthreads();

    // ---- Phase 2: streaming compute from smem ----
    const int rg = tid / 56;                // row group 0..3 (output rows rg*8..rg*8+7 in tile)
    const int tx = tid - rg * 56;           // col group 0..55 (output cols tx*4..tx*4+3)

    // smem base for this thread: input row (rg*8 + r), cols 4tx..4tx+7
    const float* sbase = sx + (rg * 8) * SROW + tx * 4;
    float* op_base = out + (size_t)plane * (HW * HW)
                   + (size_t)(tile * 32 + rg * 8) * HW + tx * 4;

    float acc[5][4];                        // cyclic window of 5 active output rows

#pragma unroll
    for (int r = 0; r < 12; r++) {
        float v[8];
        {
            const float4 a = *reinterpret_cast<const float4*>(sbase + r * SROW);
            const float4 b = *reinterpret_cast<const float4*>(sbase + r * SROW + 4);
            v[0] = a.x; v[1] = a.y; v[2] = a.z; v[3] = a.w;
            v[4] = b.x; v[5] = b.y; v[6] = b.z; v[7] = b.w;
        }

        // Input row r contributes to output rows oh = r - i, i = 0..4.
        // i == 0 is output row oh's first contribution: direct assign.
#pragma unroll
        for (int i = 0; i < 5; i++) {
            const int oh = r - i;
            if (oh >= 0 && oh < 8) {        // compile-time after unroll
                const int s = oh % 5;
                const float w0 = wf[i * 5 + 0];
                const float w1 = wf[i * 5 + 1];
                const float w2 = wf[i * 5 + 2];
                const float w3 = wf[i * 5 + 3];
                const float w4 = wf[i * 5 + 4];
#pragma unroll
                for (int q = 0; q < 4; q++) {
                    const float t0 = v[q + 0] + w0;
                    const float t1 = v[q + 1] + w1;
                    const float t2 = v[q + 2] + w2;
                    const float t3 = v[q + 3] + w3;
                    const float t4 = v[q + 4] + w4;
                    const float m  = fmaxf(fmaxf(t0, t1), t2);
                    if (i == 0) {
                        acc[s][q] = fmaxf(m, fmaxf(t3, t4));
                    } else {
                        const float n = fmaxf(fmaxf(t3, t4), acc[s][q]);
                        acc[s][q] = fmaxf(m, n);
                    }
                }
            }
        }

        // Output row oh = r - 4 complete: store as one aligned float4.
        if (r >= 4) {
            const int oh = r - 4;
            const int s  = oh % 5;
            float4 t;
            t.x = acc[s][0]; t.y = acc[s][1]; t.z = acc[s][2]; t.w = acc[s][3];
            *reinterpret_cast<float4*>(op_base + oh * HW) = t;
        }
    }
}

extern "C" void kernel_launch(void* const* d_in, const int* in_sizes, int n_in,
                              void* d_out, int out_size)
{
    const float* x = (const float*)d_in[0];
    const float* w = (const float*)d_in[1];
    float* out     = (float*)d_out;
    dim3 grid(7, 256);                      // 7 row-tiles x 256 planes
    tropical_conv_kernel<<<grid, 224>>>(x, w, out);
}

// round 13
// speedup vs baseline: 1.2705x; 1.2705x over previous
#include <cuda_runtime.h>
#include <cuda_fp16.h>
#include <math.h>

// Tropical (max-plus) depthwise 5x5 conv, stride 1, pad 2 (-inf), dilation 1.
// x: [8,32,224,224] f32, kernel: [32,1,5,5] f32, out same shape (f32).
// out[b,c,h,w] = max_{i,j} ( x_pad[b,c,h+i,w+j] + kflip[c,i,j] ).
//
// R12: fp16x2 packed math (HADD2/HMNMX2) — halves the tap instruction count.
//  - f32 loads converted to half2 pairs p0..p3 (4 cvt/row); odd-shift pairs
//    s0..s2 built with one PRMT each (__byte_perm 0x5432).
//  - Output pair A=(o0,o1) taps: p0,s0,p1,s1,p2 ; pair B=(o2,o3): p1,s1,p2,s2,p3,
//    each + replicated half2 weight, max-reduced with __hmax2 trees
//    (i==0 init fusion, acc dep-depth 1).
//  - acc = cyclic 5-row window of 2 half2 per row; stores convert back to f32.
//  - Same tiling as the 33.3us fp32 kernel: 4-wide x 8-tall per thread,
//    2 aligned float4 loads/row, predicated float2 stores,
//    57 col-groups x 28 row-groups x 256 planes, 1596 blocks of 256, (256,4).

#define HW 224
#define NEG_INF (-INFINITY)

__device__ __forceinline__ half2 shift_pair(half2 a, half2 b) {
    // (a.hi, b.lo): bytes [a.b2, a.b3, b.b0, b.b1]
    unsigned ua = *reinterpret_cast<unsigned*>(&a);
    unsigned ub = *reinterpret_cast<unsigned*>(&b);
    unsigned r  = __byte_perm(ua, ub, 0x5432);
    return *reinterpret_cast<half2*>(&r);
}

__global__ __launch_bounds__(256, 4) void tropical_conv_kernel(
    const float* __restrict__ x,
    const float* __restrict__ w,
    float* __restrict__ out)
{
    const int gid   = blockIdx.x * blockDim.x + threadIdx.x;
    const int plane = gid / 1596;           // b*32 + c, 0..255
    const int rem   = gid - plane * 1596;
    const int rg    = rem / 57;             // row group 0..27 (output rows rg*8..rg*8+7)
    const int tx    = rem - rg * 57;        // col group 0..56
    const int c     = plane & 31;

    const half2 NEG2 = __float2half2_rn(NEG_INF);

    // Flipped weights, replicated into both fp16 lanes.
    half2 wf[25];
#pragma unroll
    for (int i = 0; i < 5; i++)
#pragma unroll
        for (int j = 0; j < 5; j++)
            wf[i * 5 + j] = __float2half2_rn(__ldg(&w[c * 25 + (4 - i) * 5 + (4 - j)]));

    const float* xp = x + (size_t)plane * (HW * HW);
    float* op_base  = out + (size_t)plane * (HW * HW) + (rg * 8) * HW + (tx * 4 - 2);

    const int colL = tx * 4 - 4;            // left aligned quad: cols colL..colL+3
    const int row0 = rg * 8 - 2;            // first input row of the 12-row window

    const bool ldL = (tx > 0);
    const bool ldR = (tx < 56);

    half2 acc[5][2];                        // cyclic window: [row][pair A|B]

#pragma unroll
    for (int r = 0; r < 12; r++) {
        const int gr = row0 + r;
        const bool rowok = (gr >= 0) && (gr < HW);

        // Aligned pairs p0=(v0,v1) p1=(v2,v3) p2=(v4,v5) p3=(v6,v7)
        half2 p0, p1, p2, p3;
        if (rowok) {
            const float* rowp = xp + gr * HW + colL;
            if (ldL) {
                const float4 t = *reinterpret_cast<const float4*>(rowp);
                p0 = __floats2half2_rn(t.x, t.y);
                p1 = __floats2half2_rn(t.z, t.w);
            } else { p0 = NEG2; p1 = NEG2; }
            if (ldR) {
                const float4 t = *reinterpret_cast<const float4*>(rowp + 4);
                p2 = __floats2half2_rn(t.x, t.y);
                p3 = __floats2half2_rn(t.z, t.w);
            } else { p2 = NEG2; p3 = NEG2; }
        } else {
            p0 = NEG2; p1 = NEG2; p2 = NEG2; p3 = NEG2;
        }
        // Odd-shift pairs s0=(v1,v2) s1=(v3,v4) s2=(v5,v6)
        const half2 s0 = shift_pair(p0, p1);
        const half2 s1 = shift_pair(p1, p2);
        const half2 s2 = shift_pair(p2, p3);

        // Input row r contributes to output rows oh = r - i, i = 0..4.
        // i == 0 is output row oh's first contribution: direct assign.
#pragma unroll
        for (int i = 0; i < 5; i++) {
            const int oh = r - i;
            if (oh >= 0 && oh < 8) {        // compile-time after unroll
                const int s = oh % 5;
                const half2 w0 = wf[i * 5 + 0];
                const half2 w1 = wf[i * 5 + 1];
                const half2 w2 = wf[i * 5 + 2];
                const half2 w3 = wf[i * 5 + 3];
                const half2 w4 = wf[i * 5 + 4];

                // Pair A = outputs (o0,o1): taps (v[j],v[j+1])
                {
                    const half2 a0 = __hadd2(p0, w0);
                    const half2 a1 = __hadd2(s0, w1);
                    const half2 a2 = __hadd2(p1, w2);
                    const half2 a3 = __hadd2(s1, w3);
                    const half2 a4 = __hadd2(p2, w4);
                    const half2 m  = __hmax2(__hmax2(a0, a1), a2);
                    const half2 n  = (i == 0) ? __hmax2(a3, a4)
                                              : __hmax2(__hmax2(a3, a4), acc[s][0]);
                    acc[s][0] = __hmax2(m, n);
                }
                // Pair B = outputs (o2,o3): taps (v[2+j],v[3+j])
                {
                    const half2 b0 = __hadd2(p1, w0);
                    const half2 b1 = __hadd2(s1, w1);
                    const half2 b2 = __hadd2(p2, w2);
                    const half2 b3 = __hadd2(s2, w3);
                    const half2 b4 = __hadd2(p3, w4);
                    const half2 m  = __hmax2(__hmax2(b0, b1), b2);
                    const half2 n  = (i == 0) ? __hmax2(b3, b4)
                                              : __hmax2(__hmax2(b3, b4), acc[s][1]);
                    acc[s][1] = __hmax2(m, n);
                }
            }
        }

        // Output row oh = r - 4 is complete after this input row: store it.
        if (r >= 4) {
            const int oh = r - 4;
            const int s  = oh % 5;
            float* orow  = op_base + oh * HW;
            if (tx > 0) {
                const float2 fa = __half22float2(acc[s][0]);
                *reinterpret_cast<float2*>(orow) = fa;
            }
            if (tx < 56) {
                const float2 fb = __half22float2(acc[s][1]);
                *reinterpret_cast<float2*>(orow + 2) = fb;
            }
        }
    }
}

extern "C" void kernel_launch(void* const* d_in, const int* in_sizes, int n_in,
                              void* d_out, int out_size)
{
    const float* x = (const float*)d_in[0];
    const float* w = (const float*)d_in[1];
    float* out     = (float*)d_out;
    // 256 planes * 28 row-groups * 57 col-groups = 408576 threads = 1596 blocks
    tropical_conv_kernel<<<1596, 256>>>(x, w, out);
}